// round 3
// baseline (speedup 1.0000x reference)
#include <cuda_runtime.h>
#include <math.h>
#include <stdint.h>

#define N_LEVELS 16
#define N_POINTS 524288
#define HASH_MASK 0x7FFFFu       // hashed level size = 2^19 exactly
#define P1 2654435761u
#define P2 805459861u

// Dense-level resolutions: res_l = ceil(16 * 2^(7l/15)); levels 0..4 are dense
// (res^3 <= 2^19): 16, 23, 31, 43, 59.
__constant__ unsigned c_res[5] = {16u, 23u, 31u, 43u, 59u};

struct Scales { float s[N_LEVELS]; };

// Block = 256 threads = 16 points x 16 levels.
//   pi = tid & 15  (point within block)   lv = tid >> 4  (level)
// => levels are uniform per half-warp; only warp 2 (levels 4,5) straddles the
// dense/hashed branch. Output coalescing restored via a padded SMEM transpose.
__global__ __launch_bounds__(256) void hashenc_kernel(
    const float*  __restrict__ inputs,     // [N_POINTS, 3]
    const float2* __restrict__ emb,        // [total_entries] of float2
    const int*    __restrict__ offs,       // [17]
    float2*       __restrict__ out,        // [N_POINTS * 16] float2
    Scales sc)
{
    __shared__ float  s_in[48];            // 16 points x 3 coords
    __shared__ float2 s_out[16 * 17];      // padded stride 17 -> 2-way max conflict

    unsigned tid = threadIdx.x;

    // Coalesced staging of this block's 16 points (48 floats)
    if (tid < 48u)
        s_in[tid] = inputs[blockIdx.x * 48u + tid];
    __syncthreads();

    unsigned pi = tid & 15u;
    unsigned lv = tid >> 4;

    float x = s_in[pi * 3 + 0];
    float y = s_in[pi * 3 + 1];
    float z = s_in[pi * 3 + 2];

    float scale = sc.s[lv];
    // plain fp32 multiply (matches jnp inputs*scale bit-exactly)
    float px = x * scale, py = y * scale, pz = z * scale;
    float fx0 = floorf(px), fy0 = floorf(py), fz0 = floorf(pz);
    float fx = px - fx0, fy = py - fy0, fz = pz - fz0;
    unsigned gx = (unsigned)fx0, gy = (unsigned)fy0, gz = (unsigned)fz0;

    unsigned base = (unsigned)__ldg(&offs[lv]);

    float2 e[8];
    if (lv >= 5u) {
        // hashed: idx = (cx*1 ^ cy*P1 ^ cz*P2) & (2^19-1)
        // __ldcg: table is 4MB (L1 hit rate ~5%) — don't allocate in L1,
        // keep L1 for the dense coarse tables. Adjacent x-pairs still merge
        // at the L2 sector level.
        unsigned hy0 = gy * P1, hy1 = hy0 + P1;
        unsigned hz0 = gz * P2, hz1 = hz0 + P2;
        unsigned s00 = hy0 ^ hz0, s10 = hy1 ^ hz0;
        unsigned s01 = hy0 ^ hz1, s11 = hy1 ^ hz1;
        unsigned x0 = gx, x1 = gx + 1u;
        unsigned idx[8];
        idx[0] = (x0 ^ s00) & HASH_MASK;
        idx[1] = (x1 ^ s00) & HASH_MASK;
        idx[2] = (x0 ^ s10) & HASH_MASK;
        idx[3] = (x1 ^ s10) & HASH_MASK;
        idx[4] = (x0 ^ s01) & HASH_MASK;
        idx[5] = (x1 ^ s01) & HASH_MASK;
        idx[6] = (x0 ^ s11) & HASH_MASK;
        idx[7] = (x1 ^ s11) & HASH_MASK;
#pragma unroll
        for (int c = 0; c < 8; c++)
            e[c] = __ldcg(&emb[base + idx[c]]);
    } else {
        // dense: row-major within res^3, corners clamped to res-1; __ldg so
        // these small tables (32KB..1.6MB) stay L1-resident.
        unsigned res = c_res[lv];
        unsigned rm1 = res - 1u;
        unsigned rr  = res * res;
        unsigned x0 = min(gx, rm1),       x1 = min(gx + 1u, rm1);
        unsigned y0 = min(gy, rm1) * res, y1 = min(gy + 1u, rm1) * res;
        unsigned z0 = min(gz, rm1) * rr,  z1 = min(gz + 1u, rm1) * rr;
        unsigned idx[8];
        idx[0] = x0 + y0 + z0;
        idx[1] = x1 + y0 + z0;
        idx[2] = x0 + y1 + z0;
        idx[3] = x1 + y1 + z0;
        idx[4] = x0 + y0 + z1;
        idx[5] = x1 + y0 + z1;
        idx[6] = x0 + y1 + z1;
        idx[7] = x1 + y1 + z1;
#pragma unroll
        for (int c = 0; c < 8; c++)
            e[c] = __ldg(&emb[base + idx[c]]);
    }

    float wx[2] = {1.0f - fx, fx};
    float wy[2] = {1.0f - fy, fy};
    float wz[2] = {1.0f - fz, fz};

    float ox = 0.0f, oy = 0.0f;
#pragma unroll
    for (int c = 0; c < 8; c++) {
        float w = wx[c & 1] * wy[(c >> 1) & 1] * wz[(c >> 2) & 1];
        ox += w * e[c].x;
        oy += w * e[c].y;
    }

    // Transpose (pi,lv) -> linear (pi*16+lv) through SMEM, then coalesced
    // streaming store (keep the 67MB output out of L2).
    s_out[pi * 17 + lv] = make_float2(ox, oy);
    __syncthreads();

    unsigned o_pi = tid >> 4, o_lv = tid & 15u;
    __stcs(&out[blockIdx.x * 256u + tid], s_out[o_pi * 17 + o_lv]);
}

extern "C" void kernel_launch(void* const* d_in, const int* in_sizes, int n_in,
                              void* d_out, int out_size)
{
    const float*  inputs = (const float*)d_in[0];
    const float2* emb    = (const float2*)d_in[1];
    const int*    offs   = (const int*)d_in[2];
    float2*       out    = (float2*)d_out;

    // scale[l] = float32(16 * (2^(7/15))^l), computed in double so the float32
    // cast absorbs any sub-ulp libm difference vs numpy.
    Scales sc;
    double ratio = exp2(7.0 / 15.0);
    for (int l = 0; l < N_LEVELS; l++)
        sc.s[l] = (float)(16.0 * pow(ratio, (double)l));

    dim3 block(256);
    dim3 grid(N_POINTS / 16);   // 32768 blocks, 16 points each
    hashenc_kernel<<<grid, block>>>(inputs, emb, offs, out, sc);
}

// round 5
// speedup vs baseline: 1.2820x; 1.2820x over previous
#include <cuda_runtime.h>
#include <math.h>
#include <stdint.h>

#define N_LEVELS 16
#define N_POINTS 524288
#define HASH_MASK 0x7FFFFu       // hashed level size = 2^19 exactly
#define P1 2654435761u
#define P2 805459861u

#define NBUCK 262144             // 64^3 Morton buckets
#define SCAN_BLK 1024
#define SCAN_NBLK (NBUCK / SCAN_BLK)   // 256

// Static scratch (no allocation allowed): ~9 MB
__device__ unsigned g_hist[NBUCK];        // histogram -> exclusive offsets
__device__ unsigned g_bsum[SCAN_NBLK];    // per-block scan totals
__device__ unsigned g_perm[N_POINTS];     // sorted slot -> original point id
__device__ float    g_sorted[N_POINTS * 3]; // coords in sorted order

struct Scales { float s[N_LEVELS]; };

// ---------------- sort pipeline ----------------

__device__ __forceinline__ unsigned spread3(unsigned v) {
    v &= 0x3Fu;
    v = (v | (v << 16)) & 0x030000FFu;
    v = (v | (v << 8))  & 0x0300F00Fu;
    v = (v | (v << 4))  & 0x030C30C3u;
    v = (v | (v << 2))  & 0x09249249u;
    return v;
}

__device__ __forceinline__ unsigned bucket_of(float x, float y, float z) {
    unsigned cx = min((unsigned)(x * 64.0f), 63u);
    unsigned cy = min((unsigned)(y * 64.0f), 63u);
    unsigned cz = min((unsigned)(z * 64.0f), 63u);
    return spread3(cx) | (spread3(cy) << 1) | (spread3(cz) << 2);
}

__global__ void k_zero() {
    unsigned i = blockIdx.x * blockDim.x + threadIdx.x;
    if (i < NBUCK) g_hist[i] = 0u;
}

__global__ void k_histo(const float* __restrict__ inputs) {
    unsigned i = blockIdx.x * blockDim.x + threadIdx.x;
    float x = inputs[i * 3 + 0];
    float y = inputs[i * 3 + 1];
    float z = inputs[i * 3 + 2];
    atomicAdd(&g_hist[bucket_of(x, y, z)], 1u);
}

// Per-block exclusive scan of 1024 elems; block totals -> g_bsum
__global__ __launch_bounds__(SCAN_BLK) void k_scanA() {
    __shared__ unsigned s[SCAN_BLK];
    unsigned t = threadIdx.x;
    unsigned gid = blockIdx.x * SCAN_BLK + t;
    unsigned v = g_hist[gid];
    s[t] = v;
    __syncthreads();
    for (int d = 1; d < SCAN_BLK; d <<= 1) {
        unsigned add = (t >= (unsigned)d) ? s[t - d] : 0u;
        __syncthreads();
        s[t] += add;
        __syncthreads();
    }
    g_hist[gid] = s[t] - v;                 // exclusive within block
    if (t == SCAN_BLK - 1) g_bsum[blockIdx.x] = s[t];
}

// Exclusive scan of the 256 block totals (single block)
__global__ __launch_bounds__(SCAN_NBLK) void k_scanB() {
    __shared__ unsigned s[SCAN_NBLK];
    unsigned t = threadIdx.x;
    unsigned v = g_bsum[t];
    s[t] = v;
    __syncthreads();
    for (int d = 1; d < SCAN_NBLK; d <<= 1) {
        unsigned add = (t >= (unsigned)d) ? s[t - d] : 0u;
        __syncthreads();
        s[t] += add;
        __syncthreads();
    }
    g_bsum[t] = s[t] - v;
}

__global__ __launch_bounds__(SCAN_BLK) void k_scanC() {
    unsigned gid = blockIdx.x * SCAN_BLK + threadIdx.x;
    g_hist[gid] += g_bsum[blockIdx.x];      // global exclusive offsets
}

// Scatter: assign sorted slots, write coords in sorted order
__global__ void k_scatter(const float* __restrict__ inputs) {
    unsigned i = blockIdx.x * blockDim.x + threadIdx.x;
    float x = inputs[i * 3 + 0];
    float y = inputs[i * 3 + 1];
    float z = inputs[i * 3 + 2];
    unsigned pos = atomicAdd(&g_hist[bucket_of(x, y, z)], 1u);
    g_perm[pos] = i;
    g_sorted[pos * 3 + 0] = x;
    g_sorted[pos * 3 + 1] = y;
    g_sorted[pos * 3 + 2] = z;
}

// ---------------- main encode ----------------
// One thread per sorted point; a warp = 32 spatially-clustered points doing
// the same level/corner gather -> lane addresses collapse to few sectors on
// coarse/mid levels. NO shared memory (l1tex is the bottleneck pipe).

__global__ __launch_bounds__(256) void hashenc_main(
    const float2* __restrict__ emb,
    const int*    __restrict__ offs,
    float2*       __restrict__ out,
    Scales sc)
{
    // Dense-level resolutions: ceil(16 * 2^(7l/15)) for l=0..4 (res^3 <= 2^19).
    // Local const array in a fully-unrolled loop -> folds to immediates.
    const unsigned kRes[5] = {16u, 23u, 31u, 43u, 59u};

    unsigned i = blockIdx.x * 256u + threadIdx.x;
    // Coalesced reads of sorted coords
    float x = g_sorted[i * 3 + 0];
    float y = g_sorted[i * 3 + 1];
    float z = g_sorted[i * 3 + 2];
    unsigned p = g_perm[i];
    float* orow = (float*)out + (size_t)p * 32u;   // 128B row, 16B aligned

#pragma unroll
    for (int h = 0; h < 2; h++) {                  // two halves of 8 levels
        float acc[16];
#pragma unroll
        for (int l8 = 0; l8 < 8; l8++) {
            const int l = h * 8 + l8;
            float scale = sc.s[l];
            // plain fp32 multiply (bit-exact vs jnp inputs*scale)
            float px = x * scale, py = y * scale, pz = z * scale;
            float fx0 = floorf(px), fy0 = floorf(py), fz0 = floorf(pz);
            float fx = px - fx0, fy = py - fy0, fz = pz - fz0;
            unsigned gx = (unsigned)fx0, gy = (unsigned)fy0, gz = (unsigned)fz0;
            unsigned base = (unsigned)__ldg(&offs[l]);

            unsigned idx[8];
            if (l >= 5) {
                // hashed: (cx*1 ^ cy*P1 ^ cz*P2) & (2^19-1)
                unsigned hy0 = gy * P1, hy1 = hy0 + P1;
                unsigned hz0 = gz * P2, hz1 = hz0 + P2;
                unsigned s00 = hy0 ^ hz0, s10 = hy1 ^ hz0;
                unsigned s01 = hy0 ^ hz1, s11 = hy1 ^ hz1;
                unsigned x0 = gx, x1 = gx + 1u;
                idx[0] = (x0 ^ s00) & HASH_MASK;
                idx[1] = (x1 ^ s00) & HASH_MASK;
                idx[2] = (x0 ^ s10) & HASH_MASK;
                idx[3] = (x1 ^ s10) & HASH_MASK;
                idx[4] = (x0 ^ s01) & HASH_MASK;
                idx[5] = (x1 ^ s01) & HASH_MASK;
                idx[6] = (x0 ^ s11) & HASH_MASK;
                idx[7] = (x1 ^ s11) & HASH_MASK;
            } else {
                // dense: row-major within res^3, corners clamped to res-1
                unsigned res = kRes[l];
                unsigned rm1 = res - 1u;
                unsigned rr  = res * res;
                unsigned x0 = min(gx, rm1),       x1 = min(gx + 1u, rm1);
                unsigned y0 = min(gy, rm1) * res, y1 = min(gy + 1u, rm1) * res;
                unsigned z0 = min(gz, rm1) * rr,  z1 = min(gz + 1u, rm1) * rr;
                idx[0] = x0 + y0 + z0;
                idx[1] = x1 + y0 + z0;
                idx[2] = x0 + y1 + z0;
                idx[3] = x1 + y1 + z0;
                idx[4] = x0 + y0 + z1;
                idx[5] = x1 + y0 + z1;
                idx[6] = x0 + y1 + z1;
                idx[7] = x1 + y1 + z1;
            }

            float2 e[8];
#pragma unroll
            for (int c = 0; c < 8; c++)
                e[c] = __ldg(&emb[base + idx[c]]);

            float wx[2] = {1.0f - fx, fx};
            float wy[2] = {1.0f - fy, fy};
            float wz[2] = {1.0f - fz, fz};
            float ox = 0.0f, oy = 0.0f;
#pragma unroll
            for (int c = 0; c < 8; c++) {
                float w = wx[c & 1] * wy[(c >> 1) & 1] * wz[(c >> 2) & 1];
                ox += w * e[c].x;
                oy += w * e[c].y;
            }
            acc[l8 * 2 + 0] = ox;
            acc[l8 * 2 + 1] = oy;
        }
        // Half-row store: 4x STG.128 to this point's contiguous 128B row.
        // Streaming policy keeps the 67MB output from evicting embeddings in L2.
#pragma unroll
        for (int q = 0; q < 4; q++) {
            float4 v = make_float4(acc[q * 4 + 0], acc[q * 4 + 1],
                                   acc[q * 4 + 2], acc[q * 4 + 3]);
            __stcs((float4*)(orow + h * 16) + q, v);
        }
    }
}

// ---------------- launch ----------------

extern "C" void kernel_launch(void* const* d_in, const int* in_sizes, int n_in,
                              void* d_out, int out_size)
{
    const float*  inputs = (const float*)d_in[0];
    const float2* emb    = (const float2*)d_in[1];
    const int*    offs   = (const int*)d_in[2];
    float2*       out    = (float2*)d_out;

    // scale[l] = float32(16 * (2^(7/15))^l), computed in double so the float32
    // cast absorbs any sub-ulp libm difference vs numpy.
    Scales sc;
    double ratio = exp2(7.0 / 15.0);
    for (int l = 0; l < N_LEVELS; l++)
        sc.s[l] = (float)(16.0 * pow(ratio, (double)l));

    k_zero   <<<NBUCK / 1024, 1024>>>();
    k_histo  <<<N_POINTS / 256, 256>>>(inputs);
    k_scanA  <<<SCAN_NBLK, SCAN_BLK>>>();
    k_scanB  <<<1, SCAN_NBLK>>>();
    k_scanC  <<<SCAN_NBLK, SCAN_BLK>>>();
    k_scatter<<<N_POINTS / 256, 256>>>(inputs);
    hashenc_main<<<N_POINTS / 256, 256>>>(emb, offs, out, sc);
}